// round 11
// baseline (speedup 1.0000x reference)
#include <cuda_runtime.h>
#include <cuda_fp16.h>
#include <math.h>

#define BB 8
#define TT 512
#define RFF 16
#define HID 64
#define NH 16
#define TBL_N 4096
#define TWO_PI_F 6.283185307179586f
#define INV_PI_F 0.31830988618379067154f
#define INV_SQRT2_F 0.70710678118654752440f
#define INV_SQRT_2PI_F 0.39894228040143267794f

static __device__ __forceinline__ unsigned h2_as_u32(__half2 h) {
    return *reinterpret_cast<unsigned*>(&h);
}
static __device__ __forceinline__ __half2 u32_as_h2(unsigned u) {
    return *reinterpret_cast<__half2*>(&u);
}

// Table row (64B per node), packed as 4 quadrant chunks of 16B:
//   chunk q = { v[4q..4q+3], w[4q..4q+3] }  (8 halves)
// v = g(x_i), w = g'(x_i)/TBL_N (pre-scaled for node-unit delta).
__device__ __align__(128) static __half g_tbl[(TBL_N + 2) * 2 * NH];

// ---------------------------------------------------------------------------
// Build kernel (separate launch; register-rich version — no shared cap).
// 4 lanes per node; lane q computes hidden units [16q,16q+16); quartet
// shfl-reduce; lane q writes quadrant chunk q.
// ---------------------------------------------------------------------------
__global__ void __launch_bounds__(256) build_table_kernel(
    const float* __restrict__ phase,   // [16]
    const float* __restrict__ W1,      // [32,64]
    const float* __restrict__ b1,      // [64]
    const float* __restrict__ W2,      // [64,16]
    const float* __restrict__ b2)      // [16]
{
    __shared__ float sW1[2 * RFF * HID];
    __shared__ float sW2[HID * NH];
    __shared__ float sb1[HID];
    __shared__ float sb2[NH];
    __shared__ float sph[RFF];

    const int tid = threadIdx.x;
    for (int i = tid; i < 2 * RFF * HID; i += blockDim.x) sW1[i] = W1[i];
    for (int i = tid; i < HID * NH;     i += blockDim.x) sW2[i] = W2[i];
    if (tid < HID) sb1[tid] = b1[tid];
    if (tid < NH)  sb2[tid] = b2[tid];
    if (tid < RFF) sph[tid] = phase[tid];
    __syncthreads();

    const int gid = blockIdx.x * blockDim.x + tid;
    int node = gid >> 2;
    const int q = gid & 3;
    if (node > TBL_N) node = TBL_N;   // duplicates write identical data

    const float d = (float)node * (1.0f / (float)TBL_N);

    // freqs = logspace(log10 2, log10 64, 16) = 2^(1 + k/3)
    // sin(2*pi*f*d + phi) = sin(pi*(2*f*d + phi/pi)) -> sincospif
    float fsin[RFF], fcos[RFF], omg[RFF];
#pragma unroll
    for (int k = 0; k < RFF; k++) {
        const float f = exp2f(1.0f + (float)k * (1.0f / 3.0f));
        omg[k] = TWO_PI_F * f;
        const float y = fmaf(2.0f * f, d, sph[k] * INV_PI_F);
        sincospif(y, &fsin[k], &fcos[k]);
    }

    float o[NH], od[NH];
#pragma unroll
    for (int e = 0; e < NH; e++) { o[e] = (q == 0) ? sb2[e] : 0.0f; od[e] = 0.0f; }

    const int j0 = q * (HID / 4);
    for (int jj = 0; jj < HID / 4; jj++) {
        const int j = j0 + jj;
        float z = sb1[j], zp = 0.0f;
#pragma unroll
        for (int k = 0; k < RFF; k++) {
            const float ws = sW1[k * HID + j];
            const float wc = sW1[(RFF + k) * HID + j];
            z  = fmaf(fsin[k], ws, z);
            z  = fmaf(fcos[k], wc, z);
            zp = fmaf(omg[k] * fcos[k], ws, zp);
            zp = fmaf(-omg[k] * fsin[k], wc, zp);
        }
        const float Phi = 0.5f * (1.0f + erff(z * INV_SQRT2_F));
        const float phi = INV_SQRT_2PI_F * __expf(-0.5f * z * z);
        const float h  = z * Phi;                 // exact gelu
        const float hp = (Phi + z * phi) * zp;    // d gelu(z)/dd
#pragma unroll
        for (int e = 0; e < NH; e++) {
            const float w2 = sW2[j * NH + e];
            o[e]  = fmaf(h,  w2, o[e]);
            od[e] = fmaf(hp, w2, od[e]);
        }
    }

    // reduce partials across the 4-lane quartet
#pragma unroll
    for (int e = 0; e < NH; e++) {
        o[e]  += __shfl_xor_sync(0xffffffffu, o[e],  1);
        o[e]  += __shfl_xor_sync(0xffffffffu, o[e],  2);
        od[e] += __shfl_xor_sync(0xffffffffu, od[e], 1);
        od[e] += __shfl_xor_sync(0xffffffffu, od[e], 2);
    }

    // quadrant chunk q: { v[4q..4q+3], w[4q..4q+3] }
    const float dscale = 1.0f / (float)TBL_N;
    uint4 pk;
    pk.x = h2_as_u32(__floats2half2_rn(o[4 * q + 0],  o[4 * q + 1]));
    pk.y = h2_as_u32(__floats2half2_rn(o[4 * q + 2],  o[4 * q + 3]));
    pk.z = h2_as_u32(__floats2half2_rn(od[4 * q + 0] * dscale, od[4 * q + 1] * dscale));
    pk.w = h2_as_u32(__floats2half2_rn(od[4 * q + 2] * dscale, od[4 * q + 3] * dscale));
    reinterpret_cast<uint4*>(g_tbl + (size_t)node * 2 * NH)[q] = pk;
}

// ---------------------------------------------------------------------------
// Bias kernel: one block per (b, t); 8 warps x 64 s each.
// Lane decomposition: part = lane&3 (head quadrant, 4 heads), sub = lane>>2.
// Each lane handles 4 CONSECUTIVE s (s0 = warp*64 + step*32 + 4*sub), loading
// 4 random 16B row-chunks (1 LDG.128 each) and storing one float4 of 4
// consecutive s per head (STG.128). An 8-lane part-group covers 32 s = one
// full 128B line per head per step -> store wavefronts halved vs R6.
// ---------------------------------------------------------------------------
__global__ void __launch_bounds__(256) bias_kernel(
    const float* __restrict__ centers,   // [B*T]
    const int*   __restrict__ mask,      // [B*T] bool stored as int32
    float* __restrict__ out)             // [B, NH, T, T]
{
    const int row = blockIdx.x;
    const int b = row >> 9;
    const int t = row & (TT - 1);

    const float ct = centers[row];
    const float mt = (mask[row] != 0) ? 1.0f : 0.0f;

    const int lane = threadIdx.x & 31;
    const int warp = threadIdx.x >> 5;
    const int sub  = lane >> 2;        // 0..7
    const int part = lane & 3;         // head quadrant

    const float* __restrict__ cb = centers + b * TT;
    const int*   __restrict__ mb = mask + b * TT;

    const size_t plane = (size_t)TT * TT;
    float* __restrict__ oh =
        out + ((size_t)b * NH * TT + (size_t)t) * TT + (size_t)(4 * part) * plane;

#pragma unroll
    for (int step = 0; step < 2; step++) {
        const int s0 = warp * 64 + step * 32 + 4 * sub;

        const float4 cs4 = *reinterpret_cast<const float4*>(cb + s0);
        const int4   m4  = *reinterpret_cast<const int4*>(mb + s0);

        float m[4], delta[4];
        uint4 rch[4];
        {
            const float csa[4] = {cs4.x, cs4.y, cs4.z, cs4.w};
            const int   mma[4] = {m4.x, m4.y, m4.z, m4.w};
#pragma unroll
            for (int j = 0; j < 4; j++) {
                m[j] = (mma[j] != 0) ? mt : 0.0f;
                const float u = fabsf(ct - csa[j]) * (float)TBL_N;
                const int   i = __float2int_rn(u);
                delta[j] = (u - (float)i) * m[j];
                rch[j] = __ldg(reinterpret_cast<const uint4*>(
                             g_tbl + (size_t)i * 2 * NH) + part);
            }
        }

        float* o = oh + s0;
#pragma unroll
        for (int c = 0; c < 2; c++) {
            // heads 4*part + 2c, 4*part + 2c + 1 : v pair in rch[j] word c,
            // w pair in word 2 + c
            float4 r0, r1;
            float* pr0 = &r0.x;
            float* pr1 = &r1.x;
#pragma unroll
            for (int j = 0; j < 4; j++) {
                const unsigned* w32 = &rch[j].x;
                const float2 v2 = __half22float2(u32_as_h2(w32[c]));
                const float2 w2 = __half22float2(u32_as_h2(w32[2 + c]));
                pr0[j] = fmaf(w2.x, delta[j], v2.x * m[j]);
                pr1[j] = fmaf(w2.y, delta[j], v2.y * m[j]);
            }
            __stcs(reinterpret_cast<float4*>(o + (size_t)(2 * c) * plane), r0);
            __stcs(reinterpret_cast<float4*>(o + (size_t)(2 * c + 1) * plane), r1);
        }
    }
}

// ---------------------------------------------------------------------------
// Inputs (metadata order): centers01 [8,512] f32, mask [8,512] bool(int32),
// bias_phase [16] f32, W1 [32,64] f32, b1 [64] f32, W2 [64,16] f32, b2 [16] f32.
// Output: [8,16,512,512] f32.
// ---------------------------------------------------------------------------
extern "C" void kernel_launch(void* const* d_in, const int* in_sizes, int n_in,
                              void* d_out, int out_size)
{
    const float* centers = (const float*)d_in[0];
    const int*   mask    = (const int*)d_in[1];
    const float* phase   = (const float*)d_in[2];
    const float* W1      = (const float*)d_in[3];
    const float* b1      = (const float*)d_in[4];
    const float* W2      = (const float*)d_in[5];
    const float* b2      = (const float*)d_in[6];
    float*       out     = (float*)d_out;

    const int build_threads = (TBL_N + 1) * 4;
    build_table_kernel<<<(build_threads + 255) / 256, 256>>>(phase, W1, b1, W2, b2);
    bias_kernel<<<BB * TT, 256>>>(centers, mask, out);
}